// round 1
// baseline (speedup 1.0000x reference)
#include <cuda_runtime.h>

#define NN   50000
#define NE   800000
#define FIN  16
#define HIDC 32
#define NH   4
#define HC   128
#define NCLS 5
#define EF   8

// ---------------- scratch (static device allocation; no cudaMalloc) ----------
__device__ int   g_is64;
__device__ int   g_deg[NN];
__device__ int   g_cursor[NN];
__device__ int   g_row[NN + 1];
__device__ int   g_srce[NE];
__device__ int   g_dste[NE];
__device__ int   g_srcs[NE];          // src ids sorted by dst
__device__ float g_ae1[NE * 4];       // per-edge attention logits term, layer 1 (sorted)
__device__ float g_ae2[NE * 4];       // layer 2 (sorted)
__device__ float g_asrc[NN * 4];
__device__ float g_adst[NN * 4];
__device__ float g_buf1[NN * HC];     // xp of current layer
__device__ float g_buf2[NN * HC];     // h (layer output)

__device__ __forceinline__ float lrelu(float v) { return v > 0.f ? v : 0.2f * v; }
__device__ __forceinline__ float elu1(float v)  { return v > 0.f ? v : expm1f(v); }

// ---------------- init: zero degree histogram, set is64 flag ----------------
__global__ void k_init() {
    int i = blockIdx.x * blockDim.x + threadIdx.x;
    if (i < NN) g_deg[i] = 0;
    if (i == 0) g_is64 = 1;
}

// detect int64 vs int32 edge_index: int64 little-endian -> high words all zero
__global__ void k_detect(const unsigned* __restrict__ ei_words) {
    int i = blockIdx.x * blockDim.x + threadIdx.x;   // 2048 probes
    if (i < 2048) {
        if (ei_words[2 * i + 1] != 0u) g_is64 = 0;
    }
}

__global__ void k_convert(const void* __restrict__ ei) {
    int e = blockIdx.x * blockDim.x + threadIdx.x;
    if (e >= NE) return;
    int s, d;
    if (g_is64) {
        const long long* p = (const long long*)ei;
        s = (int)p[e]; d = (int)p[NE + e];
    } else {
        const int* p = (const int*)ei;
        s = p[e]; d = p[NE + e];
    }
    g_srce[e] = s; g_dste[e] = d;
}

__global__ void k_hist() {
    int e = blockIdx.x * blockDim.x + threadIdx.x;
    if (e < NE) atomicAdd(&g_deg[g_dste[e]], 1);
}

// single-block exclusive scan of g_deg -> g_row, g_cursor
__global__ void k_scan() {
    __shared__ int warpsum[32];
    __shared__ int sbase;
    int t = threadIdx.x, lane = t & 31, wid = t >> 5;
    if (t == 0) sbase = 0;
    __syncthreads();
    for (int base = 0; base < NN; base += 1024) {
        int i = base + t;
        int v = (i < NN) ? g_deg[i] : 0;
        int incl = v;
        #pragma unroll
        for (int off = 1; off < 32; off <<= 1) {
            int u = __shfl_up_sync(0xffffffffu, incl, off);
            if (lane >= off) incl += u;
        }
        if (lane == 31) warpsum[wid] = incl;
        __syncthreads();
        if (wid == 0) {
            int w = warpsum[lane];
            int wi = w;
            #pragma unroll
            for (int off = 1; off < 32; off <<= 1) {
                int u = __shfl_up_sync(0xffffffffu, wi, off);
                if (lane >= off) wi += u;
            }
            warpsum[lane] = wi - w;   // exclusive warp offset
        }
        __syncthreads();
        int excl = incl - v + warpsum[wid] + sbase;
        if (i < NN) { g_row[i] = excl; g_cursor[i] = excl; }
        __syncthreads();
        if (t == 1023) sbase = excl + v;
        __syncthreads();
    }
    if (threadIdx.x == 0) g_row[NN] = sbase;
}

// edge encoder MLP + fold into a_e terms, scattered into dst-sorted order
__global__ void k_edge_encode(const float* __restrict__ eattr,
                              const float* __restrict__ w1, const float* __restrict__ b1,
                              const float* __restrict__ w2, const float* __restrict__ b2,
                              const float* __restrict__ We1, const float* __restrict__ aew1,
                              const float* __restrict__ We2, const float* __restrict__ aew2) {
    __shared__ float sw1[HIDC * EF];   // 256
    __shared__ float sb1[HIDC];
    __shared__ float sw2[NH * HIDC];   // 128
    __shared__ float sb2[NH];
    __shared__ float sv[32];           // v1 [4x4] then v2 [4x4]
    int t = threadIdx.x;
    if (t < HIDC * EF) sw1[t] = w1[t];
    if (t < HIDC)      sb1[t] = b1[t];
    if (t < NH * HIDC) sw2[t] = w2[t];
    if (t < NH)        sb2[t] = b2[t];
    if (t < 32) {
        const float* We = (t < 16) ? We1 : We2;
        const float* aw = (t < 16) ? aew1 : aew2;
        int idx = t & 15, h = idx >> 2, k = idx & 3;
        float s = 0.f;
        for (int c = 0; c < HIDC; c++) s += We[(h * HIDC + c) * NH + k] * aw[h * HIDC + c];
        sv[t] = s;
    }
    __syncthreads();
    int e = blockIdx.x * blockDim.x + t;
    if (e >= NE) return;
    const float4* ea4 = (const float4*)(eattr + e * EF);
    float4 p0 = ea4[0], p1 = ea4[1];
    float a[8] = {p0.x, p0.y, p0.z, p0.w, p1.x, p1.y, p1.z, p1.w};
    float o0 = sb2[0], o1 = sb2[1], o2 = sb2[2], o3 = sb2[3];
    #pragma unroll
    for (int j = 0; j < HIDC; j++) {
        float h = sb1[j];
        #pragma unroll
        for (int k = 0; k < EF; k++) h = fmaf(a[k], sw1[j * EF + k], h);
        h = fmaxf(h, 0.f);
        o0 = fmaf(h, sw2[j], o0);
        o1 = fmaf(h, sw2[HIDC + j], o1);
        o2 = fmaf(h, sw2[2 * HIDC + j], o2);
        o3 = fmaf(h, sw2[3 * HIDC + j], o3);
    }
    int src = g_srce[e];
    int dst = g_dste[e];
    int pos = atomicAdd(&g_cursor[dst], 1);
    g_srcs[pos] = src;
    float4 r1, r2;
    r1.x = o0 * sv[0]  + o1 * sv[1]  + o2 * sv[2]  + o3 * sv[3];
    r1.y = o0 * sv[4]  + o1 * sv[5]  + o2 * sv[6]  + o3 * sv[7];
    r1.z = o0 * sv[8]  + o1 * sv[9]  + o2 * sv[10] + o3 * sv[11];
    r1.w = o0 * sv[12] + o1 * sv[13] + o2 * sv[14] + o3 * sv[15];
    r2.x = o0 * sv[16] + o1 * sv[17] + o2 * sv[18] + o3 * sv[19];
    r2.y = o0 * sv[20] + o1 * sv[21] + o2 * sv[22] + o3 * sv[23];
    r2.z = o0 * sv[24] + o1 * sv[25] + o2 * sv[26] + o3 * sv[27];
    r2.w = o0 * sv[28] + o1 * sv[29] + o2 * sv[30] + o3 * sv[31];
    ((float4*)g_ae1)[pos] = r1;
    ((float4*)g_ae2)[pos] = r2;
}

// xp = x @ W.T  for FIN=16 input (layer 1)
__global__ void k_transform_small(const float* __restrict__ xin,
                                  const float* __restrict__ W,
                                  float* __restrict__ out) {
    __shared__ float4 Ws[HC * FIN / 4];   // 512 float4 = 8 KB
    int t = threadIdx.x;
    for (int i = t; i < HC * FIN / 4; i += blockDim.x) Ws[i] = ((const float4*)W)[i];
    __syncthreads();
    int idx = blockIdx.x * blockDim.x + t;
    if (idx >= NN * HC) return;
    int n = idx >> 7, c = idx & 127;
    const float4* xr = (const float4*)(xin + n * FIN);
    float acc = 0.f;
    #pragma unroll
    for (int k4 = 0; k4 < FIN / 4; k4++) {
        float4 xv = xr[k4];
        float4 wv = Ws[c * (FIN / 4) + k4];
        acc += xv.x * wv.x + xv.y * wv.y + xv.z * wv.z + xv.w * wv.w;
    }
    out[idx] = acc;
}

// xp = h @ W.T for 128->128 (layer 2). Tiled: 32 nodes/block, W^T in smem.
#define TM 32
#define SMEM_BIG ((HC * HC + TM * HC) * 4)
__global__ __launch_bounds__(512, 2) void k_transform_big(const float* __restrict__ hin,
                                                          const float* __restrict__ W,
                                                          float* __restrict__ out) {
    extern __shared__ float smem[];
    float* Wt = smem;            // [k][c], 64 KB
    float* xs = smem + HC * HC;  // [nl][k], 16 KB
    int t = threadIdx.x;
    int n0 = blockIdx.x * TM;
    for (int i = t; i < HC * HC; i += 512) {
        int c = i >> 7, k = i & 127;
        Wt[k * HC + c] = W[i];
    }
    for (int i = t; i < TM * HC; i += 512) {
        int nl = i >> 7, n = n0 + nl;
        xs[i] = (n < NN) ? hin[n * HC + (i & 127)] : 0.f;
    }
    __syncthreads();
    int nl = t >> 4;            // 0..31
    int cb = (t & 15) * 8;      // output channel base
    float acc[8];
    #pragma unroll
    for (int j = 0; j < 8; j++) acc[j] = 0.f;
    const float4* Wt4 = (const float4*)Wt;
    #pragma unroll 4
    for (int k = 0; k < HC; k++) {
        float xv = xs[nl * HC + k];
        float4 wa = Wt4[k * (HC / 4) + (cb >> 2)];
        float4 wb = Wt4[k * (HC / 4) + (cb >> 2) + 1];
        acc[0] = fmaf(xv, wa.x, acc[0]); acc[1] = fmaf(xv, wa.y, acc[1]);
        acc[2] = fmaf(xv, wa.z, acc[2]); acc[3] = fmaf(xv, wa.w, acc[3]);
        acc[4] = fmaf(xv, wb.x, acc[4]); acc[5] = fmaf(xv, wb.y, acc[5]);
        acc[6] = fmaf(xv, wb.z, acc[6]); acc[7] = fmaf(xv, wb.w, acc[7]);
    }
    int n = n0 + nl;
    if (n < NN) {
        float4* o4 = (float4*)(out + n * HC + cb);
        o4[0] = make_float4(acc[0], acc[1], acc[2], acc[3]);
        o4[1] = make_float4(acc[4], acc[5], acc[6], acc[7]);
    }
}

// a_src[n,h], a_dst[n,h] from xp
__global__ void k_attn(const float* __restrict__ xp,
                       const float* __restrict__ as_w,
                       const float* __restrict__ ad_w) {
    __shared__ float ss[HC], sd[HC];
    int t = threadIdx.x;  // 128
    ss[t] = as_w[t]; sd[t] = ad_w[t];
    __syncthreads();
    int h = t >> 5, lane = t & 31;
    for (int it = 0; it < 16; it++) {
        int n = blockIdx.x * 16 + it;
        float v = xp[n * HC + t];
        float ps = v * ss[t], pd = v * sd[t];
        #pragma unroll
        for (int off = 16; off; off >>= 1) {
            ps += __shfl_xor_sync(0xffffffffu, ps, off);
            pd += __shfl_xor_sync(0xffffffffu, pd, off);
        }
        if (lane == 0) { g_asrc[n * 4 + h] = ps; g_adst[n * 4 + h] = pd; }
    }
}

// per-dst-node softmax + aggregation. One warp per node. Two passes, no atomics.
__global__ void k_gat(const float* __restrict__ xp,
                      const float* __restrict__ ae,
                      const float* __restrict__ bias,
                      float* __restrict__ out) {
    int wib = threadIdx.x >> 5, lane = threadIdx.x & 31;
    int n = blockIdx.x * 8 + wib;
    if (n >= NN) return;
    int row = g_row[n], end = g_row[n + 1];
    float4 ad4 = ((const float4*)g_adst)[n];
    float ad_l = (lane == 0) ? ad4.x : (lane == 1) ? ad4.y : (lane == 2) ? ad4.z : ad4.w;
    // pass 1: per-head max
    float m0 = -3.0e38f, m1 = -3.0e38f, m2 = -3.0e38f, m3 = -3.0e38f;
    for (int j = row + lane; j < end; j += 32) {
        int s = g_srcs[j];
        float4 as4 = ((const float4*)g_asrc)[s];
        float4 ae4 = ((const float4*)ae)[j];
        m0 = fmaxf(m0, lrelu(as4.x + ad4.x + ae4.x));
        m1 = fmaxf(m1, lrelu(as4.y + ad4.y + ae4.y));
        m2 = fmaxf(m2, lrelu(as4.z + ad4.z + ae4.z));
        m3 = fmaxf(m3, lrelu(as4.w + ad4.w + ae4.w));
    }
    #pragma unroll
    for (int off = 16; off; off >>= 1) {
        m0 = fmaxf(m0, __shfl_xor_sync(0xffffffffu, m0, off));
        m1 = fmaxf(m1, __shfl_xor_sync(0xffffffffu, m1, off));
        m2 = fmaxf(m2, __shfl_xor_sync(0xffffffffu, m2, off));
        m3 = fmaxf(m3, __shfl_xor_sync(0xffffffffu, m3, off));
    }
    float ml = (lane == 0) ? m0 : (lane == 1) ? m1 : (lane == 2) ? m2 : m3;
    // pass 2: accumulate e and e*xp
    float s0 = 0.f, s1 = 0.f, s2 = 0.f, s3 = 0.f;
    float a0 = 0.f, a1 = 0.f, a2 = 0.f, a3 = 0.f;
    for (int j = row; j < end; j++) {
        int s = g_srcs[j];
        float w = 0.f;
        if (lane < 4) {
            float l = lrelu(g_asrc[s * 4 + lane] + ad_l + ae[j * 4 + lane]);
            w = __expf(l - ml);
        }
        float w0 = __shfl_sync(0xffffffffu, w, 0);
        float w1 = __shfl_sync(0xffffffffu, w, 1);
        float w2 = __shfl_sync(0xffffffffu, w, 2);
        float w3 = __shfl_sync(0xffffffffu, w, 3);
        s0 += w0; s1 += w1; s2 += w2; s3 += w3;
        const float* xr = xp + s * HC;
        a0 = fmaf(w0, xr[lane],      a0);
        a1 = fmaf(w1, xr[32 + lane], a1);
        a2 = fmaf(w2, xr[64 + lane], a2);
        a3 = fmaf(w3, xr[96 + lane], a3);
    }
    float i0 = 1.f / (s0 + 1e-16f), i1 = 1.f / (s1 + 1e-16f);
    float i2 = 1.f / (s2 + 1e-16f), i3 = 1.f / (s3 + 1e-16f);
    int b = n * HC;
    out[b + lane]      = elu1(a0 * i0 + bias[lane]);
    out[b + 32 + lane] = elu1(a1 * i1 + bias[32 + lane]);
    out[b + 64 + lane] = elu1(a2 * i2 + bias[64 + lane]);
    out[b + 96 + lane] = elu1(a3 * i3 + bias[96 + lane]);
}

// final: logits = (h2 + x@skip_w.T + skip_b) @ cls_w.T + cls_b
__global__ void k_final(const float* __restrict__ h2, const float* __restrict__ x,
                        const float* __restrict__ skip_w, const float* __restrict__ skip_b,
                        const float* __restrict__ cls_w, const float* __restrict__ cls_b,
                        float* __restrict__ out) {
    __shared__ float sw[HC * FIN];
    __shared__ float sb[HC];
    __shared__ float scw[NCLS * HC];
    __shared__ float red[NCLS * 4];
    int t = threadIdx.x;  // 128
    for (int i = t; i < HC * FIN; i += 128) sw[i] = skip_w[i];
    sb[t] = skip_b[t];
    for (int i = t; i < NCLS * HC; i += 128) scw[i] = cls_w[i];
    __syncthreads();
    int wid = t >> 5, lane = t & 31;
    for (int it = 0; it < 16; it++) {
        int n = blockIdx.x * 16 + it;
        const float4* xr = (const float4*)(x + n * FIN);
        float4 x0 = xr[0], x1 = xr[1], x2 = xr[2], x3 = xr[3];
        const float* wr = &sw[t * FIN];
        float sk = sb[t];
        sk = fmaf(x0.x, wr[0],  sk); sk = fmaf(x0.y, wr[1],  sk);
        sk = fmaf(x0.z, wr[2],  sk); sk = fmaf(x0.w, wr[3],  sk);
        sk = fmaf(x1.x, wr[4],  sk); sk = fmaf(x1.y, wr[5],  sk);
        sk = fmaf(x1.z, wr[6],  sk); sk = fmaf(x1.w, wr[7],  sk);
        sk = fmaf(x2.x, wr[8],  sk); sk = fmaf(x2.y, wr[9],  sk);
        sk = fmaf(x2.z, wr[10], sk); sk = fmaf(x2.w, wr[11], sk);
        sk = fmaf(x3.x, wr[12], sk); sk = fmaf(x3.y, wr[13], sk);
        sk = fmaf(x3.z, wr[14], sk); sk = fmaf(x3.w, wr[15], sk);
        float v = h2[n * HC + t] + sk;
        #pragma unroll
        for (int k = 0; k < NCLS; k++) {
            float p = v * scw[k * HC + t];
            #pragma unroll
            for (int off = 16; off; off >>= 1) p += __shfl_xor_sync(0xffffffffu, p, off);
            if (lane == 0) red[k * 4 + wid] = p;
        }
        __syncthreads();
        if (t < NCLS) out[n * NCLS + t] = red[t * 4] + red[t * 4 + 1] + red[t * 4 + 2] + red[t * 4 + 3] + cls_b[t];
        __syncthreads();
    }
}

extern "C" void kernel_launch(void* const* d_in, const int* in_sizes, int n_in,
                              void* d_out, int out_size) {
    const float* x      = (const float*)d_in[0];
    const void*  ei     = d_in[1];
    const float* eattr  = (const float*)d_in[2];
    const float* ee_w1  = (const float*)d_in[3];
    const float* ee_b1  = (const float*)d_in[4];
    const float* ee_w2  = (const float*)d_in[5];
    const float* ee_b2  = (const float*)d_in[6];
    const float* g1_W   = (const float*)d_in[7];
    const float* g1_We  = (const float*)d_in[8];
    const float* g1_as  = (const float*)d_in[9];
    const float* g1_ad  = (const float*)d_in[10];
    const float* g1_ae  = (const float*)d_in[11];
    const float* g1_b   = (const float*)d_in[12];
    const float* g2_W   = (const float*)d_in[13];
    const float* g2_We  = (const float*)d_in[14];
    const float* g2_as  = (const float*)d_in[15];
    const float* g2_ad  = (const float*)d_in[16];
    const float* g2_ae  = (const float*)d_in[17];
    const float* g2_b   = (const float*)d_in[18];
    const float* skip_w = (const float*)d_in[19];
    const float* skip_b = (const float*)d_in[20];
    const float* cls_w  = (const float*)d_in[21];
    const float* cls_b  = (const float*)d_in[22];
    float* out = (float*)d_out;

    static_assert(SMEM_BIG <= 100 * 1024, "smem");
    cudaFuncSetAttribute(k_transform_big, cudaFuncAttributeMaxDynamicSharedMemorySize, SMEM_BIG);

    float *buf1, *buf2;
    cudaGetSymbolAddress((void**)&buf1, g_buf1);
    cudaGetSymbolAddress((void**)&buf2, g_buf2);

    // --- CSR build + edge encoding ---
    k_init<<<(NN + 255) / 256, 256>>>();
    k_detect<<<8, 256>>>((const unsigned*)ei);
    k_convert<<<NE / 256, 256>>>(ei);
    k_hist<<<NE / 256, 256>>>();
    k_scan<<<1, 1024>>>();
    k_edge_encode<<<NE / 256, 256>>>(eattr, ee_w1, ee_b1, ee_w2, ee_b2,
                                     g1_We, g1_ae, g2_We, g2_ae);
    // --- layer 1 ---
    k_transform_small<<<NN * HC / 256, 256>>>(x, g1_W, buf1);
    k_attn<<<NN / 16, 128>>>(buf1, g1_as, g1_ad);
    k_gat<<<NN / 8, 256>>>(buf1, g_ae1, g1_b, buf2);
    // --- layer 2 ---
    k_transform_big<<<(NN + TM - 1) / TM, 512, SMEM_BIG>>>(buf2, g2_W, buf1);
    k_attn<<<NN / 16, 128>>>(buf1, g2_as, g2_ad);
    k_gat<<<NN / 8, 256>>>(buf1, g_ae2, g2_b, buf2);
    // --- final ---
    k_final<<<NN / 16, 128>>>(buf2, x, skip_w, skip_b, cls_w, cls_b, out);
}

// round 3
// speedup vs baseline: 1.3170x; 1.3170x over previous
#include <cuda_runtime.h>

#define NN   50000
#define NE   800000
#define FIN  16
#define HIDC 32
#define NH   4
#define HC   128
#define NCLS 5
#define EF   8

// ---------------- scratch (static device allocation; no cudaMalloc) ----------
__device__ int   g_is64;
__device__ int   g_deg[NN];
__device__ int   g_cursor[NN];
__device__ int   g_row[NN + 1];
__device__ int   g_srce[NE];
__device__ int   g_dste[NE];
__device__ int   g_srcs[NE];          // src ids sorted by dst
__device__ float g_ae1[NE * 4];       // per-edge attention logit term, layer 1 (sorted)
__device__ float g_ae2[NE * 4];       // layer 2 (sorted)
__device__ float g_asrc[NN * 4];
__device__ float g_adst[NN * 4];
__device__ float g_buf1[NN * HC];
__device__ float g_buf2[NN * HC];

#define SCB 256
#define NSB ((NN + SCB - 1) / SCB)    // 196
__device__ int g_bsum[NSB];

__device__ __forceinline__ float lrelu(float v) { return v > 0.f ? v : 0.2f * v; }
__device__ __forceinline__ float elu1(float v)  { return v > 0.f ? v : expm1f(v); }

// packed f32x2 helpers (Blackwell): ptxas never auto-fuses these from C++
__device__ __forceinline__ unsigned long long packf2(float v) {
    unsigned long long r; asm("mov.b64 %0, {%1, %1};" : "=l"(r) : "f"(v)); return r;
}
__device__ __forceinline__ unsigned long long ffma2(unsigned long long a,
                                                    unsigned long long b,
                                                    unsigned long long c) {
    unsigned long long d;
    asm("fma.rn.f32x2 %0, %1, %2, %3;" : "=l"(d) : "l"(a), "l"(b), "l"(c));
    return d;
}

// ---------------- prologue ----------------
__global__ void k_init() {
    int i = blockIdx.x * blockDim.x + threadIdx.x;
    if (i < NN) g_deg[i] = 0;
    if (i == 0) g_is64 = 1;
}

__global__ void k_detect(const unsigned* __restrict__ ei_words) {
    int i = blockIdx.x * blockDim.x + threadIdx.x;
    if (i < 2048) {
        if (ei_words[2 * i + 1] != 0u) g_is64 = 0;
    }
}

__global__ void k_convert_hist(const void* __restrict__ ei) {
    int e = blockIdx.x * blockDim.x + threadIdx.x;
    if (e >= NE) return;
    int s, d;
    if (g_is64) {
        const long long* p = (const long long*)ei;
        s = (int)p[e]; d = (int)p[NE + e];
    } else {
        const int* p = (const int*)ei;
        s = p[e]; d = p[NE + e];
    }
    g_srce[e] = s; g_dste[e] = d;
    atomicAdd(&g_deg[d], 1);
}

// ---------------- parallel scan: 3 small kernels ----------------
__global__ void k_scan1() {
    __shared__ int red[8];
    int t = threadIdx.x, lane = t & 31, wid = t >> 5;
    int i = blockIdx.x * SCB + t;
    int v = (i < NN) ? g_deg[i] : 0;
    #pragma unroll
    for (int off = 16; off; off >>= 1) v += __shfl_xor_sync(0xffffffffu, v, off);
    if (lane == 0) red[wid] = v;
    __syncthreads();
    if (t == 0) {
        int s = 0;
        #pragma unroll
        for (int j = 0; j < 8; j++) s += red[j];
        g_bsum[blockIdx.x] = s;
    }
}

__global__ void k_scan2() {
    __shared__ int ws[8];
    int t = threadIdx.x, lane = t & 31, wid = t >> 5;
    int v = (t < NSB) ? g_bsum[t] : 0;
    int incl = v;
    #pragma unroll
    for (int off = 1; off < 32; off <<= 1) {
        int u = __shfl_up_sync(0xffffffffu, incl, off);
        if (lane >= off) incl += u;
    }
    if (lane == 31) ws[wid] = incl;
    __syncthreads();
    if (wid == 0) {
        int x = (lane < 8) ? ws[lane] : 0;
        #pragma unroll
        for (int off = 1; off < 8; off <<= 1) {
            int u = __shfl_up_sync(0xffffffffu, x, off);
            if (lane >= off) x += u;
        }
        if (lane < 8) ws[lane] = x;
    }
    __syncthreads();
    int offset = wid ? ws[wid - 1] : 0;
    if (t < NSB) g_bsum[t] = incl - v + offset;   // exclusive block offsets
}

__global__ void k_scan3() {
    __shared__ int ws[8];
    int t = threadIdx.x, lane = t & 31, wid = t >> 5;
    int i = blockIdx.x * SCB + t;
    int v = (i < NN) ? g_deg[i] : 0;
    int incl = v;
    #pragma unroll
    for (int off = 1; off < 32; off <<= 1) {
        int u = __shfl_up_sync(0xffffffffu, incl, off);
        if (lane >= off) incl += u;
    }
    if (lane == 31) ws[wid] = incl;
    __syncthreads();
    if (wid == 0) {
        int x = (lane < 8) ? ws[lane] : 0;
        #pragma unroll
        for (int off = 1; off < 8; off <<= 1) {
            int u = __shfl_up_sync(0xffffffffu, x, off);
            if (lane >= off) x += u;
        }
        if (lane < 8) ws[lane] = x;
    }
    __syncthreads();
    int offset = (wid ? ws[wid - 1] : 0) + g_bsum[blockIdx.x];
    int excl = incl - v + offset;
    if (i < NN) { g_row[i] = excl; g_cursor[i] = excl; }
    if (i == 0) g_row[NN] = NE;
}

// ---------------- edge encoder MLP + a_e fold, dst-sorted scatter -----------
__global__ void k_edge_encode(const float* __restrict__ eattr,
                              const float* __restrict__ w1, const float* __restrict__ b1,
                              const float* __restrict__ w2, const float* __restrict__ b2,
                              const float* __restrict__ We1, const float* __restrict__ aew1,
                              const float* __restrict__ We2, const float* __restrict__ aew2) {
    __shared__ float sw1[HIDC * EF];
    __shared__ float sb1[HIDC];
    __shared__ float sw2[NH * HIDC];
    __shared__ float sb2[NH];
    __shared__ float sv[32];
    int t = threadIdx.x;
    if (t < HIDC * EF) sw1[t] = w1[t];
    if (t < HIDC)      sb1[t] = b1[t];
    if (t < NH * HIDC) sw2[t] = w2[t];
    if (t < NH)        sb2[t] = b2[t];
    if (t < 32) {
        const float* We = (t < 16) ? We1 : We2;
        const float* aw = (t < 16) ? aew1 : aew2;
        int idx = t & 15, h = idx >> 2, k = idx & 3;
        float s = 0.f;
        for (int c = 0; c < HIDC; c++)
            s = fmaf(We[(h * HIDC + c) * NH + k], aw[h * HIDC + c], s);
        sv[t] = s;
    }
    __syncthreads();
    int e = blockIdx.x * blockDim.x + t;
    if (e >= NE) return;
    const float4* ea4 = (const float4*)(eattr + e * EF);
    float4 p0 = ea4[0], p1 = ea4[1];
    float a[8] = {p0.x, p0.y, p0.z, p0.w, p1.x, p1.y, p1.z, p1.w};
    float o0 = sb2[0], o1 = sb2[1], o2 = sb2[2], o3 = sb2[3];
    #pragma unroll
    for (int j = 0; j < HIDC; j++) {
        float h = sb1[j];
        #pragma unroll
        for (int k = 0; k < EF; k++) h = fmaf(a[k], sw1[j * EF + k], h);
        h = fmaxf(h, 0.f);
        o0 = fmaf(h, sw2[j], o0);
        o1 = fmaf(h, sw2[HIDC + j], o1);
        o2 = fmaf(h, sw2[2 * HIDC + j], o2);
        o3 = fmaf(h, sw2[3 * HIDC + j], o3);
    }
    int src = g_srce[e];
    int dst = g_dste[e];
    int pos = atomicAdd(&g_cursor[dst], 1);
    g_srcs[pos] = src;
    float4 r1, r2;
    r1.x = o0 * sv[0]  + o1 * sv[1]  + o2 * sv[2]  + o3 * sv[3];
    r1.y = o0 * sv[4]  + o1 * sv[5]  + o2 * sv[6]  + o3 * sv[7];
    r1.z = o0 * sv[8]  + o1 * sv[9]  + o2 * sv[10] + o3 * sv[11];
    r1.w = o0 * sv[12] + o1 * sv[13] + o2 * sv[14] + o3 * sv[15];
    r2.x = o0 * sv[16] + o1 * sv[17] + o2 * sv[18] + o3 * sv[19];
    r2.y = o0 * sv[20] + o1 * sv[21] + o2 * sv[22] + o3 * sv[23];
    r2.z = o0 * sv[24] + o1 * sv[25] + o2 * sv[26] + o3 * sv[27];
    r2.w = o0 * sv[28] + o1 * sv[29] + o2 * sv[30] + o3 * sv[31];
    ((float4*)g_ae1)[pos] = r1;
    ((float4*)g_ae2)[pos] = r2;
}

// ---------------- xp = x @ W.T (FIN=16) + fused a_src/a_dst epilogue --------
__global__ void k_transform_small(const float* __restrict__ xin,
                                  const float* __restrict__ W,
                                  const float* __restrict__ as_w,
                                  const float* __restrict__ ad_w,
                                  float* __restrict__ out) {
    __shared__ float Ws[HC * FIN];
    __shared__ float sas[HC], sad[HC];
    int t = threadIdx.x;
    for (int i = t; i < HC * FIN; i += blockDim.x) Ws[i] = W[i];
    if (t < HC) { sas[t] = as_w[t]; sad[t] = ad_w[t]; }
    __syncthreads();
    int idx = blockIdx.x * blockDim.x + t;
    int n = idx >> 7, c = idx & 127;
    const float4* xr = (const float4*)(xin + n * FIN);
    float acc = 0.f;
    #pragma unroll
    for (int k4 = 0; k4 < FIN / 4; k4++) {
        float4 xv = xr[k4];
        acc = fmaf(xv.x, Ws[c * FIN + k4 * 4 + 0], acc);
        acc = fmaf(xv.y, Ws[c * FIN + k4 * 4 + 1], acc);
        acc = fmaf(xv.z, Ws[c * FIN + k4 * 4 + 2], acc);
        acc = fmaf(xv.w, Ws[c * FIN + k4 * 4 + 3], acc);
    }
    out[idx] = acc;
    // epilogue: a_src/a_dst (warp = one head of one node)
    float ps = acc * sas[c], pd = acc * sad[c];
    #pragma unroll
    for (int off = 16; off; off >>= 1) {
        ps += __shfl_xor_sync(0xffffffffu, ps, off);
        pd += __shfl_xor_sync(0xffffffffu, pd, off);
    }
    if ((t & 31) == 0) {
        int h = c >> 5;
        g_asrc[n * 4 + h] = ps;
        g_adst[n * 4 + h] = pd;
    }
}

// ---------------- xp = h @ W.T (128->128) + fused a_src/a_dst ---------------
// TM=64 nodes/block, 512 threads, 2 nodes/thread, packed f32x2 FMA.
#define TM 64
#define SMEM_BIG ((HC * HC + TM * HC + 2 * HC) * 4)
__global__ __launch_bounds__(512, 1) void k_transform_big(const float* __restrict__ hin,
                                                          const float* __restrict__ W,
                                                          const float* __restrict__ as_w,
                                                          const float* __restrict__ ad_w,
                                                          float* __restrict__ out) {
    extern __shared__ float smem[];
    float* Wt  = smem;                     // [k][c], 64 KB
    float* xs  = smem + HC * HC;           // [nl][k], 32 KB
    float* sas = smem + HC * HC + TM * HC;
    float* sad = sas + HC;
    int t = threadIdx.x;
    int n0 = blockIdx.x * TM;
    for (int i = t; i < HC * HC; i += 512) {
        int c = i >> 7, k = i & 127;
        Wt[k * HC + c] = W[i];
    }
    for (int i = t; i < TM * HC; i += 512) {
        int nl = i >> 7, n = n0 + nl;
        xs[i] = (n < NN) ? hin[n * HC + (i & 127)] : 0.f;
    }
    if (t < HC) { sas[t] = as_w[t]; sad[t] = ad_w[t]; }
    __syncthreads();
    int nr = t >> 4;            // 0..31 : nodes nr and nr+32
    int cb = (t & 15) * 8;      // output channel base
    unsigned long long acc0[4], acc1[4];
    #pragma unroll
    for (int j = 0; j < 4; j++) { acc0[j] = 0ull; acc1[j] = 0ull; }
    #pragma unroll 4
    for (int k = 0; k < HC; k++) {
        unsigned long long x0 = packf2(xs[nr * HC + k]);
        unsigned long long x1 = packf2(xs[(nr + 32) * HC + k]);
        const ulonglong2* wp = (const ulonglong2*)(Wt + k * HC + cb);
        ulonglong2 wa = wp[0];
        ulonglong2 wb = wp[1];
        acc0[0] = ffma2(x0, wa.x, acc0[0]); acc0[1] = ffma2(x0, wa.y, acc0[1]);
        acc0[2] = ffma2(x0, wb.x, acc0[2]); acc0[3] = ffma2(x0, wb.y, acc0[3]);
        acc1[0] = ffma2(x1, wa.x, acc1[0]); acc1[1] = ffma2(x1, wa.y, acc1[1]);
        acc1[2] = ffma2(x1, wb.x, acc1[2]); acc1[3] = ffma2(x1, wb.y, acc1[3]);
    }
    float a0[8], a1[8];
    #pragma unroll
    for (int j = 0; j < 4; j++) {
        float2 f0 = *(float2*)&acc0[j];
        float2 f1 = *(float2*)&acc1[j];
        a0[2 * j] = f0.x; a0[2 * j + 1] = f0.y;
        a1[2 * j] = f1.x; a1[2 * j + 1] = f1.y;
    }
    int na = n0 + nr, nb = n0 + nr + 32;
    if (na < NN) {
        float4* o4 = (float4*)(out + na * HC + cb);
        o4[0] = make_float4(a0[0], a0[1], a0[2], a0[3]);
        o4[1] = make_float4(a0[4], a0[5], a0[6], a0[7]);
    }
    if (nb < NN) {
        float4* o4 = (float4*)(out + nb * HC + cb);
        o4[0] = make_float4(a1[0], a1[1], a1[2], a1[3]);
        o4[1] = make_float4(a1[4], a1[5], a1[6], a1[7]);
    }
    // epilogue: a_src/a_dst. Groups of 4 lanes (same nr) cover one head.
    float ps0 = 0.f, pd0 = 0.f, ps1 = 0.f, pd1 = 0.f;
    #pragma unroll
    for (int j = 0; j < 8; j++) {
        ps0 = fmaf(a0[j], sas[cb + j], ps0);
        pd0 = fmaf(a0[j], sad[cb + j], pd0);
        ps1 = fmaf(a1[j], sas[cb + j], ps1);
        pd1 = fmaf(a1[j], sad[cb + j], pd1);
    }
    #pragma unroll
    for (int off = 1; off < 4; off <<= 1) {
        ps0 += __shfl_xor_sync(0xffffffffu, ps0, off);
        pd0 += __shfl_xor_sync(0xffffffffu, pd0, off);
        ps1 += __shfl_xor_sync(0xffffffffu, ps1, off);
        pd1 += __shfl_xor_sync(0xffffffffu, pd1, off);
    }
    if ((t & 3) == 0) {
        int h = (t & 15) >> 2;
        if (na < NN) { g_asrc[na * 4 + h] = ps0; g_adst[na * 4 + h] = pd0; }
        if (nb < NN) { g_asrc[nb * 4 + h] = ps1; g_adst[nb * 4 + h] = pd1; }
    }
}

// ---------------- per-dst softmax + aggregation, single fused pass ----------
__global__ void k_gat(const float* __restrict__ xp,
                      const float* __restrict__ ae,
                      const float* __restrict__ bias,
                      float* __restrict__ out) {
    int warp = (blockIdx.x * blockDim.x + threadIdx.x) >> 5;
    int lane = threadIdx.x & 31;
    if (warp >= NN) return;
    int n = warp;
    int row = g_row[n], end = g_row[n + 1];
    float4 ad = ((const float4*)g_adst)[n];
    float a0 = 0.f, a1 = 0.f, a2 = 0.f, a3 = 0.f;
    float s0 = 0.f, s1 = 0.f, s2 = 0.f, s3 = 0.f;
    for (int base = row; base < end; base += 32) {
        int e = base + lane;
        bool valid = e < end;
        int s = 0;
        float wx = 0.f, wy = 0.f, wz = 0.f, ww = 0.f;
        if (valid) {
            s = __ldg(&g_srcs[e]);
            float4 as = __ldg(&((const float4*)g_asrc)[s]);
            float4 av = __ldg(&((const float4*)ae)[e]);
            wx = __expf(lrelu(as.x + ad.x + av.x));
            wy = __expf(lrelu(as.y + ad.y + av.y));
            wz = __expf(lrelu(as.z + ad.z + av.z));
            ww = __expf(lrelu(as.w + ad.w + av.w));
        }
        int cnt = min(32, end - base);
        #pragma unroll 4
        for (int t = 0; t < cnt; t++) {
            int   ss = __shfl_sync(0xffffffffu, s, t);
            float vx = __shfl_sync(0xffffffffu, wx, t);
            float vy = __shfl_sync(0xffffffffu, wy, t);
            float vz = __shfl_sync(0xffffffffu, wz, t);
            float vw = __shfl_sync(0xffffffffu, ww, t);
            const float* xr = xp + ss * HC;
            a0 = fmaf(vx, __ldg(xr + lane),      a0);
            a1 = fmaf(vy, __ldg(xr + 32 + lane), a1);
            a2 = fmaf(vz, __ldg(xr + 64 + lane), a2);
            a3 = fmaf(vw, __ldg(xr + 96 + lane), a3);
            s0 += vx; s1 += vy; s2 += vz; s3 += vw;
        }
    }
    float i0 = 1.f / (s0 + 1e-16f), i1 = 1.f / (s1 + 1e-16f);
    float i2 = 1.f / (s2 + 1e-16f), i3 = 1.f / (s3 + 1e-16f);
    int b = n * HC;
    out[b + lane]      = elu1(a0 * i0 + bias[lane]);
    out[b + 32 + lane] = elu1(a1 * i1 + bias[32 + lane]);
    out[b + 64 + lane] = elu1(a2 * i2 + bias[64 + lane]);
    out[b + 96 + lane] = elu1(a3 * i3 + bias[96 + lane]);
}

// ---------------- final: logits = (h2 + x@skip_w.T + skip_b) @ cls_w.T + cls_b
__global__ void k_final(const float* __restrict__ h2, const float* __restrict__ x,
                        const float* __restrict__ skip_w, const float* __restrict__ skip_b,
                        const float* __restrict__ cls_w, const float* __restrict__ cls_b,
                        float* __restrict__ out) {
    __shared__ float sw[HC * FIN];
    __shared__ float sb[HC];
    __shared__ float scw[NCLS * HC];
    __shared__ float red[NCLS * 4];
    int t = threadIdx.x;  // 128
    for (int i = t; i < HC * FIN; i += 128) sw[i] = skip_w[i];
    sb[t] = skip_b[t];
    for (int i = t; i < NCLS * HC; i += 128) scw[i] = cls_w[i];
    __syncthreads();
    int wid = t >> 5, lane = t & 31;
    for (int it = 0; it < 16; it++) {
        int n = blockIdx.x * 16 + it;
        const float4* xr = (const float4*)(x + n * FIN);
        float4 x0 = xr[0], x1 = xr[1], x2 = xr[2], x3 = xr[3];
        float xv[16] = {x0.x, x0.y, x0.z, x0.w, x1.x, x1.y, x1.z, x1.w,
                        x2.x, x2.y, x2.z, x2.w, x3.x, x3.y, x3.z, x3.w};
        const float* wr = &sw[t * FIN];
        float sk = sb[t];
        #pragma unroll
        for (int k = 0; k < FIN; k++) sk = fmaf(xv[k], wr[k], sk);
        float v = h2[n * HC + t] + sk;
        #pragma unroll
        for (int k = 0; k < NCLS; k++) {
            float p = v * scw[k * HC + t];
            #pragma unroll
            for (int off = 16; off; off >>= 1) p += __shfl_xor_sync(0xffffffffu, p, off);
            if (lane == 0) red[k * 4 + wid] = p;
        }
        __syncthreads();
        if (t < NCLS)
            out[n * NCLS + t] = red[t * 4] + red[t * 4 + 1] + red[t * 4 + 2] + red[t * 4 + 3] + cls_b[t];
        __syncthreads();
    }
}

extern "C" void kernel_launch(void* const* d_in, const int* in_sizes, int n_in,
                              void* d_out, int out_size) {
    const float* x      = (const float*)d_in[0];
    const void*  ei     = d_in[1];
    const float* eattr  = (const float*)d_in[2];
    const float* ee_w1  = (const float*)d_in[3];
    const float* ee_b1  = (const float*)d_in[4];
    const float* ee_w2  = (const float*)d_in[5];
    const float* ee_b2  = (const float*)d_in[6];
    const float* g1_W   = (const float*)d_in[7];
    const float* g1_We  = (const float*)d_in[8];
    const float* g1_as  = (const float*)d_in[9];
    const float* g1_ad  = (const float*)d_in[10];
    const float* g1_ae  = (const float*)d_in[11];
    const float* g1_b   = (const float*)d_in[12];
    const float* g2_W   = (const float*)d_in[13];
    const float* g2_We  = (const float*)d_in[14];
    const float* g2_as  = (const float*)d_in[15];
    const float* g2_ad  = (const float*)d_in[16];
    const float* g2_ae  = (const float*)d_in[17];
    const float* g2_b   = (const float*)d_in[18];
    const float* skip_w = (const float*)d_in[19];
    const float* skip_b = (const float*)d_in[20];
    const float* cls_w  = (const float*)d_in[21];
    const float* cls_b  = (const float*)d_in[22];
    float* out = (float*)d_out;

    static_assert(SMEM_BIG <= 100 * 1024, "smem");
    cudaFuncSetAttribute(k_transform_big, cudaFuncAttributeMaxDynamicSharedMemorySize, SMEM_BIG);

    float *buf1, *buf2;
    cudaGetSymbolAddress((void**)&buf1, g_buf1);
    cudaGetSymbolAddress((void**)&buf2, g_buf2);

    // --- CSR build + edge encoding ---
    k_init<<<(NN + 255) / 256, 256>>>();
    k_detect<<<8, 256>>>((const unsigned*)ei);
    k_convert_hist<<<NE / 256, 256>>>(ei);
    k_scan1<<<NSB, SCB>>>();
    k_scan2<<<1, 256>>>();
    k_scan3<<<NSB, SCB>>>();
    k_edge_encode<<<NE / 256, 256>>>(eattr, ee_w1, ee_b1, ee_w2, ee_b2,
                                     g1_We, g1_ae, g2_We, g2_ae);
    // --- layer 1 ---
    k_transform_small<<<NN * HC / 256, 256>>>(x, g1_W, g1_as, g1_ad, buf1);
    k_gat<<<(NN * 32 + 255) / 256, 256>>>(buf1, g_ae1, g1_b, buf2);
    // --- layer 2 ---
    k_transform_big<<<(NN + TM - 1) / TM, 512, SMEM_BIG>>>(buf2, g2_W, g2_as, g2_ad, buf1);
    k_gat<<<(NN * 32 + 255) / 256, 256>>>(buf1, g_ae2, g2_b, buf2);
    // --- final ---
    k_final<<<NN / 16, 128>>>(buf2, x, skip_w, skip_b, cls_w, cls_b, out);
}